// round 16
// baseline (speedup 1.0000x reference)
#include <cuda_runtime.h>
#include <cuda_fp16.h>
#include <cstddef>

// Problem dims (fixed): (B=2, C=1, D=160, H=192, W=160) fp32, WIN=9 box, zero pad
#define Bn 2
#define Dn 160
#define Hn 192
#define Wn 160
#define Rr 4
#define HW (Hn*Wn)
#define DHW (Dn*HW)
#define NB (Bn*DHW)          // 9,830,400 outputs
#define NCH 5
#define NQ (Wn/4)            // 40 w-quads

// K1 (fused W+H filter): HSPLIT=4 (R12/R15 measured-best shape)
#define HSPLIT 4
#define HCHUNK (Hn/HSPLIT)   // 48
#define HSUB (HCHUNK/4)      // 12 output rows per thread

// K2 (D-filter + cc): DSPLIT=16 -> 1536 blocks -> ~78% occ target
#define DSPLIT 16
#define DCHUNK (Dn/DSPLIT)   // 10
#define NROWS 4
#define NPART (Bn*(Hn/NROWS)*DSPLIT)   // 1536

// Scratch TRANSPOSED fp16 with padded D axis, holding WH-filtered sums:
//   [ch][b][h][dp][w],  dp = d + PADLO,  dp in [0, DP)
// Pad planes are NEVER written; __device__ globals are zero-initialized,
// so they are permanently zero -> K2's D loop is branch-free.
#define DP 176
#define PADLO 8
#define NBP ((size_t)Bn*Hn*DP*Wn)      // 10,813,440 els per channel
__device__ uint2 g_buf[NCH * NBP / 4]; // ~108.1 MB, 8B-aligned, zero-init
__device__ double g_part[NPART];
__device__ unsigned int g_done = 0;

typedef unsigned long long u64;

__device__ __forceinline__ float4 f4zero() { return make_float4(0.f,0.f,0.f,0.f); }
#define ADD4(S,V) do{ S.x+=V.x; S.y+=V.y; S.z+=V.z; S.w+=V.w; }while(0)
#define SUB4(S,V) do{ S.x-=V.x; S.y-=V.y; S.z-=V.z; S.w-=V.w; }while(0)

// ---- packed f32x2 primitives (FFMA2/FADD2/FMUL2 — PTX-only on sm_103a) ----
__device__ __forceinline__ u64 pk2(float a, float b) {
    u64 r; asm("mov.b64 %0, {%1, %2};" : "=l"(r) : "f"(a), "f"(b)); return r;
}
__device__ __forceinline__ void upk2(u64 v, float& a, float& b) {
    asm("mov.b64 {%0, %1}, %2;" : "=f"(a), "=f"(b) : "l"(v));
}
__device__ __forceinline__ u64 add2(u64 a, u64 b) {
    u64 r; asm("add.rn.f32x2 %0, %1, %2;" : "=l"(r) : "l"(a), "l"(b)); return r;
}
__device__ __forceinline__ u64 mul2(u64 a, u64 b) {
    u64 r; asm("mul.rn.f32x2 %0, %1, %2;" : "=l"(r) : "l"(a), "l"(b)); return r;
}
__device__ __forceinline__ u64 fma2(u64 a, u64 b, u64 c) {
    u64 r; asm("fma.rn.f32x2 %0, %1, %2, %3;" : "=l"(r) : "l"(a), "l"(b), "l"(c)); return r;
}
// a - b, per lane (via fma with packed -1.0f: exact)
__device__ __forceinline__ u64 sub2(u64 a, u64 b) {
    return fma2(b, 0xBF800000BF800000ULL, a);
}

// one 8B load -> 4 floats
__device__ __forceinline__ float4 ldh4(const __half* a) {
    const uint2 u = *(const uint2*)a;
    const __half2 h0 = *(const __half2*)&u.x;
    const __half2 h1 = *(const __half2*)&u.y;
    const float2 lo = __half22float2(h0);
    const float2 hi = __half22float2(h1);
    return make_float4(lo.x, lo.y, hi.x, hi.y);
}
// 4 floats -> one 8B store
__device__ __forceinline__ void sth4(__half* a, float4 v) {
    const __half2 h0 = __floats2half2_rn(v.x, v.y);
    const __half2 h1 = __floats2half2_rn(v.z, v.w);
    uint2 u;
    u.x = *(const unsigned*)&h0;
    u.y = *(const unsigned*)&h1;
    *(uint2*)a = u;
}

// 12 consecutive scalars -> four 9-tap sliding sums (scalar)
__device__ __forceinline__ float4 slide9(const float v[12]) {
    float s = v[0]+v[1]+v[2]+v[3]+v[4]+v[5]+v[6]+v[7]+v[8];
    float4 o;
    o.x = s; s += v[9]  - v[0];
    o.y = s; s += v[10] - v[1];
    o.z = s; s += v[11] - v[2];
    o.w = s;
    return o;
}

// 12 packed lane-pairs -> four packed 9-tap sliding sums
__device__ __forceinline__ void slide9p(const u64 v[12], u64 o[4]) {
    u64 s = add2(add2(add2(add2(v[0],v[1]), add2(v[2],v[3])),
                      add2(add2(v[4],v[5]), add2(v[6],v[7]))), v[8]);
    o[0] = s;
    s = add2(s, sub2(v[9],  v[0])); o[1] = s;
    s = add2(s, sub2(v[10], v[1])); o[2] = s;
    s = add2(s, sub2(v[11], v[2])); o[3] = s;
}

// One raw row's 12-value neighborhood for a w-quad (zero-padded at W edges)
// -> 5-channel W-sums, channel-packed: o01 = (sumI, sumJ), o23 = (sumI2, sumJ2),
// o4 = sumIJ (scalar float4 over the 4 outputs).
__device__ __forceinline__ void row_wsums_p(const float* __restrict__ rI,
                                            const float* __restrict__ rJ,
                                            int wq,
                                            u64 o01[4], u64 o23[4], float4& o4) {
    const float4 aL = (wq > 0)      ? *(const float4*)(rI - 4) : f4zero();
    const float4 aC =                 *(const float4*)(rI);
    const float4 aR = (wq < NQ - 1) ? *(const float4*)(rI + 4) : f4zero();
    const float4 bL = (wq > 0)      ? *(const float4*)(rJ - 4) : f4zero();
    const float4 bC =                 *(const float4*)(rJ);
    const float4 bR = (wq < NQ - 1) ? *(const float4*)(rJ + 4) : f4zero();

    const float x[12] = {aL.x,aL.y,aL.z,aL.w, aC.x,aC.y,aC.z,aC.w, aR.x,aR.y,aR.z,aR.w};
    const float y[12] = {bL.x,bL.y,bL.z,bL.w, bC.x,bC.y,bC.z,bC.w, bR.x,bR.y,bR.z,bR.w};

    u64 xy[12];
#pragma unroll
    for (int k = 0; k < 12; ++k) xy[k] = pk2(x[k], y[k]);
    slide9p(xy, o01);

#pragma unroll
    for (int k = 0; k < 12; ++k) xy[k] = mul2(xy[k], xy[k]);   // (x^2, y^2)
    slide9p(xy, o23);

    float p[12];
#pragma unroll
    for (int k = 0; k < 12; ++k) p[k] = x[k] * y[k];
    o4 = slide9(p);
}

// ---------------------------------------------------------------------------
// K1: fused W+H 9-tap box sums, channel-packed f32x2 math, fp32 accumulate,
// no smem, no syncs. Rolling H window; subtract side recomputes the leaving
// row's W-sums from L1-resident raw rows (exact telescoping — identical
// packed ops on identical inputs). fp16 stores into TRANSPOSED padded
// scratch [ch][b][h][dp][w]. Grid: Bn*Dn*HSPLIT = 1280, block 160.
// ---------------------------------------------------------------------------
__global__ void __launch_bounds__(160)
pass_wh(const float* __restrict__ I, const float* __restrict__ J,
        __half* __restrict__ out) {
    const int blk = blockIdx.x;
    const int hs  = blk % HSPLIT;
    const int rem = blk / HSPLIT;
    const int d   = rem % Dn;
    const int b   = rem / Dn;

    const int tid  = threadIdx.x;
    const int wq   = tid % NQ;
    const int hsub = tid / NQ;                 // 0..3
    const int hbeg = hs * HCHUNK + hsub * HSUB;

    const size_t pbase = (size_t)b * DHW + (size_t)d * HW + 4*wq;
    const float* bI = I + pbase;
    const float* bJ = J + pbase;
    __half* bO = out + ((size_t)(b*Hn) * DP + (d + PADLO)) * Wn + 4*wq;

    // H accumulators: channel-packed pairs per output pixel + scalar ch4
    u64 A01[4] = {0,0,0,0};                    // (0.0f,0.0f) packed
    u64 A23[4] = {0,0,0,0};
    float4 A4 = f4zero();

    for (int r = hbeg - Rr; r <= hbeg + HSUB + Rr - 1; ++r) {
        if ((unsigned)r < (unsigned)Hn) {
            u64 o01[4], o23[4]; float4 o4;
            row_wsums_p(bI + (size_t)r*Wn, bJ + (size_t)r*Wn, wq, o01, o23, o4);
#pragma unroll
            for (int i = 0; i < 4; ++i) {
                A01[i] = add2(A01[i], o01[i]);
                A23[i] = add2(A23[i], o23[i]);
            }
            ADD4(A4, o4);
        }
        const int o = r - Rr;
        if (o >= hbeg) {
            // unpack to per-channel float4s and store fp16
            float4 S0, S1, S2, S3;
            upk2(A01[0], S0.x, S1.x); upk2(A01[1], S0.y, S1.y);
            upk2(A01[2], S0.z, S1.z); upk2(A01[3], S0.w, S1.w);
            upk2(A23[0], S2.x, S3.x); upk2(A23[1], S2.y, S3.y);
            upk2(A23[2], S2.z, S3.z); upk2(A23[3], S2.w, S3.w);

            __half* op = bO + (size_t)o * (DP * Wn);
            sth4(op + 0*NBP, S0);
            sth4(op + 1*NBP, S1);
            sth4(op + 2*NBP, S2);
            sth4(op + 3*NBP, S3);
            sth4(op + 4*NBP, A4);

            const int qr = r - 2*Rr;           // row leaving the window
            if (qr >= 0) {
                u64 o01[4], o23[4]; float4 o4;
                row_wsums_p(bI + (size_t)qr*Wn, bJ + (size_t)qr*Wn, wq, o01, o23, o4);
#pragma unroll
                for (int i = 0; i < 4; ++i) {
                    A01[i] = sub2(A01[i], o01[i]);
                    A23[i] = sub2(A23[i], o23[i]);
                }
                SUB4(A4, o4);
            }
        }
    }
}

// ---------------------------------------------------------------------------
// K2: trivial branch-free D-filter on fp16 WH-sums + cc + global mean.
// Register rolling window; add streams 320B-stride, subtract reloads are
// L1/L2-resident; pads make everything unconditional. Block: 160 = 40 quads
// x 4 h-rows. Grid: 1536 (DSPLIT=16 -> ~78% occ target).
// ---------------------------------------------------------------------------
__global__ void __launch_bounds__(160)
pass_d_cc(const __half* __restrict__ in, float* __restrict__ outscalar) {
    const int blk   = blockIdx.x;
    const int chunk = blk % DSPLIT;
    const int id    = blk / DSPLIT;
    const int hg    = id % (Hn/NROWS);
    const int b     = id / (Hn/NROWS);

    const int tid  = threadIdx.x;
    const int wq   = tid % NQ;
    const int row4 = tid / NQ;                 // 0..3
    const int h    = hg * NROWS + row4;

    const __half* pc0 = in + ((size_t)(b*Hn + h) * DP + PADLO) * Wn + 4*wq;
    const __half* pc1 = pc0 + 1*NBP;
    const __half* pc2 = pc0 + 2*NBP;
    const __half* pc3 = pc0 + 3*NBP;
    const __half* pc4 = pc0 + 4*NBP;

    const int o0 = chunk * DCHUNK;

    float4 S0=f4zero(), S1=f4zero(), S2=f4zero(), S3=f4zero(), S4=f4zero();
#pragma unroll
    for (int k = -Rr; k <= Rr; ++k) {
        const ptrdiff_t off = (ptrdiff_t)(o0 + k) * Wn;
        float4 v;
        v = ldh4(pc0 + off); ADD4(S0,v);
        v = ldh4(pc1 + off); ADD4(S1,v);
        v = ldh4(pc2 + off); ADD4(S2,v);
        v = ldh4(pc3 + off); ADD4(S3,v);
        v = ldh4(pc4 + off); ADD4(S4,v);
    }

    const float inv = 1.0f / 729.0f;
    float accf = 0.f;

    for (int o = o0; o < o0 + DCHUNK; ++o) {
        {
            const float mu1=S0.x*inv, mu2=S1.x*inv;
            const float v1=S2.x*inv-mu1*mu1, v2=S3.x*inv-mu2*mu2, cv=S4.x*inv-mu1*mu2;
            accf += __fdividef(cv*cv, v1*v2 + 1e-5f);
        }
        {
            const float mu1=S0.y*inv, mu2=S1.y*inv;
            const float v1=S2.y*inv-mu1*mu1, v2=S3.y*inv-mu2*mu2, cv=S4.y*inv-mu1*mu2;
            accf += __fdividef(cv*cv, v1*v2 + 1e-5f);
        }
        {
            const float mu1=S0.z*inv, mu2=S1.z*inv;
            const float v1=S2.z*inv-mu1*mu1, v2=S3.z*inv-mu2*mu2, cv=S4.z*inv-mu1*mu2;
            accf += __fdividef(cv*cv, v1*v2 + 1e-5f);
        }
        {
            const float mu1=S0.w*inv, mu2=S1.w*inv;
            const float v1=S2.w*inv-mu1*mu1, v2=S3.w*inv-mu2*mu2, cv=S4.w*inv-mu1*mu2;
            accf += __fdividef(cv*cv, v1*v2 + 1e-5f);
        }

        {
            const ptrdiff_t oa = (ptrdiff_t)(o + Rr + 1) * Wn;
            const ptrdiff_t os = (ptrdiff_t)(o - Rr) * Wn;
            float4 v;
            v = ldh4(pc0 + oa); ADD4(S0,v);
            v = ldh4(pc1 + oa); ADD4(S1,v);
            v = ldh4(pc2 + oa); ADD4(S2,v);
            v = ldh4(pc3 + oa); ADD4(S3,v);
            v = ldh4(pc4 + oa); ADD4(S4,v);
            v = ldh4(pc0 + os); SUB4(S0,v);
            v = ldh4(pc1 + os); SUB4(S1,v);
            v = ldh4(pc2 + os); SUB4(S2,v);
            v = ldh4(pc3 + os); SUB4(S3,v);
            v = ldh4(pc4 + os); SUB4(S4,v);
        }
    }

    // Deterministic block reduction (160 -> 1)
    __shared__ double red[160];
    const int w = tid;
    red[w] = (double)accf;
    __syncthreads();
    if (w < 32) red[w] += red[w + 128];
    __syncthreads();
#pragma unroll
    for (int s = 64; s > 0; s >>= 1) {
        if (w < s) red[w] += red[w + s];
        __syncthreads();
    }

    __shared__ int isLast;
    if (w == 0) {
        g_part[blk] = red[0];
        __threadfence();
        const unsigned v = atomicAdd(&g_done, 1u);
        isLast = (v == (unsigned)(gridDim.x - 1));
    }
    __syncthreads();

    if (isLast) {
        __threadfence();
        double a = 0.0;
        for (int i = w; i < NPART; i += 160) a += g_part[i];  // fixed order
        red[w] = a;
        __syncthreads();
        if (w < 32) red[w] += red[w + 128];
        __syncthreads();
#pragma unroll
        for (int s = 64; s > 0; s >>= 1) {
            if (w < s) red[w] += red[w + s];
            __syncthreads();
        }
        if (w == 0) {
            outscalar[0] = (float)(-red[0] / (double)NB);
            g_done = 0;   // reset for next graph replay
        }
    }
}

extern "C" void kernel_launch(void* const* d_in, const int* in_sizes, int n_in,
                              void* d_out, int out_size) {
    const float* I = (const float*)d_in[0];   // y_true
    const float* J = (const float*)d_in[1];   // y_pred
    float* out = (float*)d_out;

    void* bufraw;
    cudaGetSymbolAddress(&bufraw, g_buf);
    __half* buf = (__half*)bufraw;

    pass_wh<<<Bn * Dn * HSPLIT, 160>>>(I, J, buf);
    pass_d_cc<<<Bn * (Hn/NROWS) * DSPLIT, 160>>>(buf, out);
}

// round 17
// speedup vs baseline: 1.1489x; 1.1489x over previous
#include <cuda_runtime.h>
#include <cuda_fp16.h>
#include <cstddef>

// Problem dims (fixed): (B=2, C=1, D=160, H=192, W=160) fp32, WIN=9 box, zero pad
#define Bn 2
#define Dn 160
#define Hn 192
#define Wn 160
#define Rr 4
#define HW (Hn*Wn)
#define DHW (Dn*HW)
#define NB (Bn*DHW)          // 9,830,400 outputs
#define NCH 5
#define NQ (Wn/4)            // 40 w-quads

// K1 (fused W+H filter): HSPLIT=4, smem fp16 ring kills subtract recompute
#define HSPLIT 4
#define HCHUNK (Hn/HSPLIT)   // 48
#define HSUB (HCHUNK/4)      // 12 output rows per thread
#define RINGSLOTS 8
#define RING_BYTES (RINGSLOTS * NCH * 160 * 8)   // 51,200 B dynamic smem

// K2 (D-filter + cc): DSPLIT=10 — measured-best (42-43us), reverted
#define DSPLIT 10
#define DCHUNK (Dn/DSPLIT)   // 16
#define NROWS 4
#define NPART (Bn*(Hn/NROWS)*DSPLIT)   // 960

// Scratch TRANSPOSED fp16 with padded D axis, holding WH-filtered sums:
//   [ch][b][h][dp][w],  dp = d + PADLO,  dp in [0, DP)
// Pad planes are NEVER written; __device__ globals are zero-initialized,
// so they are permanently zero -> K2's D loop is branch-free.
#define DP 176
#define PADLO 8
#define NBP ((size_t)Bn*Hn*DP*Wn)      // 10,813,440 els per channel
__device__ uint2 g_buf[NCH * NBP / 4]; // ~108.1 MB, 8B-aligned, zero-init
__device__ double g_part[NPART];
__device__ unsigned int g_done = 0;

__device__ __forceinline__ float4 f4zero() { return make_float4(0.f,0.f,0.f,0.f); }
#define ADD4(S,V) do{ S.x+=V.x; S.y+=V.y; S.z+=V.z; S.w+=V.w; }while(0)
#define SUB4(S,V) do{ S.x-=V.x; S.y-=V.y; S.z-=V.z; S.w-=V.w; }while(0)

// fp16-quad pack/unpack (register <-> uint2)
__device__ __forceinline__ uint2 h4pack(float4 v) {
    const __half2 h0 = __floats2half2_rn(v.x, v.y);
    const __half2 h1 = __floats2half2_rn(v.z, v.w);
    uint2 u;
    u.x = *(const unsigned*)&h0;
    u.y = *(const unsigned*)&h1;
    return u;
}
__device__ __forceinline__ float4 h4unpack(uint2 u) {
    const __half2 h0 = *(const __half2*)&u.x;
    const __half2 h1 = *(const __half2*)&u.y;
    const float2 lo = __half22float2(h0);
    const float2 hi = __half22float2(h1);
    return make_float4(lo.x, lo.y, hi.x, hi.y);
}

// one 8B global load -> 4 floats
__device__ __forceinline__ float4 ldh4(const __half* a) {
    return h4unpack(*(const uint2*)a);
}
// 4 floats -> one 8B global store
__device__ __forceinline__ void sth4(__half* a, float4 v) {
    *(uint2*)a = h4pack(v);
}

// 12 consecutive scalars -> four 9-tap sliding sums
__device__ __forceinline__ float4 slide9(const float v[12]) {
    float s = v[0]+v[1]+v[2]+v[3]+v[4]+v[5]+v[6]+v[7]+v[8];
    float4 o;
    o.x = s; s += v[9]  - v[0];
    o.y = s; s += v[10] - v[1];
    o.z = s; s += v[11] - v[2];
    o.w = s;
    return o;
}

// One raw row's 12-value neighborhood for a w-quad (zero-padded at W edges)
// -> the 5 channel 9-tap W-sums.
__device__ __forceinline__ void row_wsums(const float* __restrict__ rI,
                                          const float* __restrict__ rJ,
                                          int wq,
                                          float4& w0, float4& w1, float4& w2,
                                          float4& w3, float4& w4) {
    const float4 aL = (wq > 0)      ? *(const float4*)(rI - 4) : f4zero();
    const float4 aC =                 *(const float4*)(rI);
    const float4 aR = (wq < NQ - 1) ? *(const float4*)(rI + 4) : f4zero();
    const float4 bL = (wq > 0)      ? *(const float4*)(rJ - 4) : f4zero();
    const float4 bC =                 *(const float4*)(rJ);
    const float4 bR = (wq < NQ - 1) ? *(const float4*)(rJ + 4) : f4zero();

    float x[12] = {aL.x,aL.y,aL.z,aL.w, aC.x,aC.y,aC.z,aC.w, aR.x,aR.y,aR.z,aR.w};
    float y[12] = {bL.x,bL.y,bL.z,bL.w, bC.x,bC.y,bC.z,bC.w, bR.x,bR.y,bR.z,bR.w};

    w0 = slide9(x);
    w1 = slide9(y);
    float t[12];
#pragma unroll
    for (int k = 0; k < 12; ++k) t[k] = x[k]*x[k];
    w2 = slide9(t);
#pragma unroll
    for (int k = 0; k < 12; ++k) t[k] = y[k]*y[k];
    w3 = slide9(t);
#pragma unroll
    for (int k = 0; k < 12; ++k) t[k] = x[k]*y[k];
    w4 = slide9(t);
}

// ---------------------------------------------------------------------------
// K1: fused W+H 9-tap box sums (5 stat channels), fp32 accumulate, NO syncs.
// Each row's W-sums are computed ONCE, fp16-rounded, added to the rolling H
// window, and stashed in a thread-private smem ring (8 slots, read-before-
// write); the subtract side replays the exact stashed bits -> bit-exact
// telescoping with zero recompute. fp16 stores into TRANSPOSED padded
// scratch [ch][b][h][dp][w]. Grid: Bn*Dn*HSPLIT = 1280, block 160,
// 51.2 KB dynamic smem (ring is thread-column-private: conflict-free, no bar).
// ---------------------------------------------------------------------------
__global__ void __launch_bounds__(160)
pass_wh(const float* __restrict__ I, const float* __restrict__ J,
        __half* __restrict__ out) {
    extern __shared__ uint2 ring[];   // [slot][ch][tid] : ((slot*5+ch)*160+tid)

    const int blk = blockIdx.x;
    const int hs  = blk % HSPLIT;
    const int rem = blk / HSPLIT;
    const int d   = rem % Dn;
    const int b   = rem / Dn;

    const int tid  = threadIdx.x;
    const int wq   = tid % NQ;
    const int hsub = tid / NQ;                 // 0..3
    const int hbeg = hs * HCHUNK + hsub * HSUB;

    const size_t pbase = (size_t)b * DHW + (size_t)d * HW + 4*wq;
    const float* bI = I + pbase;
    const float* bJ = J + pbase;
    __half* bO = out + ((size_t)(b*Hn) * DP + (d + PADLO)) * Wn + 4*wq;

    float4 S0=f4zero(), S1=f4zero(), S2=f4zero(), S3=f4zero(), S4=f4zero();

    for (int r = hbeg - Rr; r <= hbeg + HSUB + Rr - 1; ++r) {
        const int slot = r & (RINGSLOTS - 1);  // slot(r) == slot(r-8)
        uint2* rp = ring + (size_t)slot * (NCH * 160) + tid;

        // 1) read the leaving row's stashed W-sums BEFORE overwriting the slot
        const int o  = r - Rr;
        const int qr = r - 2*Rr;
        const bool dosub = (o >= hbeg) && (qr >= 0);
        float4 u0, u1, u2, u3, u4;
        if (dosub) {
            u0 = h4unpack(rp[0*160]);
            u1 = h4unpack(rp[1*160]);
            u2 = h4unpack(rp[2*160]);
            u3 = h4unpack(rp[3*160]);
            u4 = h4unpack(rp[4*160]);
        }

        // 2) compute this row's W-sums once, fp16-round, add + stash
        if ((unsigned)r < (unsigned)Hn) {
            float4 w0,w1,w2,w3,w4;
            row_wsums(bI + (size_t)r*Wn, bJ + (size_t)r*Wn, wq,
                      w0,w1,w2,w3,w4);
            const uint2 q0 = h4pack(w0), q1 = h4pack(w1), q2 = h4pack(w2),
                        q3 = h4pack(w3), q4 = h4pack(w4);
            // add the ROUNDED value so the later subtract telescopes exactly
            const float4 a0 = h4unpack(q0), a1 = h4unpack(q1), a2 = h4unpack(q2),
                         a3 = h4unpack(q3), a4 = h4unpack(q4);
            ADD4(S0,a0); ADD4(S1,a1); ADD4(S2,a2); ADD4(S3,a3); ADD4(S4,a4);
            rp[0*160] = q0;
            rp[1*160] = q1;
            rp[2*160] = q2;
            rp[3*160] = q3;
            rp[4*160] = q4;
        }

        // 3) emit output row o, then drop the leaving row (exact bits)
        if (o >= hbeg) {
            __half* op = bO + (size_t)o * (DP * Wn);
            sth4(op + 0*NBP, S0);
            sth4(op + 1*NBP, S1);
            sth4(op + 2*NBP, S2);
            sth4(op + 3*NBP, S3);
            sth4(op + 4*NBP, S4);
            if (dosub) {
                SUB4(S0,u0); SUB4(S1,u1); SUB4(S2,u2); SUB4(S3,u3); SUB4(S4,u4);
            }
        }
    }
}

// ---------------------------------------------------------------------------
// K2: trivial branch-free D-filter on fp16 WH-sums + cc + global mean.
// (R13/R15 measured-best shape, DSPLIT=10 — unchanged)
// ---------------------------------------------------------------------------
__global__ void __launch_bounds__(160)
pass_d_cc(const __half* __restrict__ in, float* __restrict__ outscalar) {
    const int blk   = blockIdx.x;
    const int chunk = blk % DSPLIT;
    const int id    = blk / DSPLIT;
    const int hg    = id % (Hn/NROWS);
    const int b     = id / (Hn/NROWS);

    const int tid  = threadIdx.x;
    const int wq   = tid % NQ;
    const int row4 = tid / NQ;                 // 0..3
    const int h    = hg * NROWS + row4;

    const __half* pc0 = in + ((size_t)(b*Hn + h) * DP + PADLO) * Wn + 4*wq;
    const __half* pc1 = pc0 + 1*NBP;
    const __half* pc2 = pc0 + 2*NBP;
    const __half* pc3 = pc0 + 3*NBP;
    const __half* pc4 = pc0 + 4*NBP;

    const int o0 = chunk * DCHUNK;

    float4 S0=f4zero(), S1=f4zero(), S2=f4zero(), S3=f4zero(), S4=f4zero();
#pragma unroll
    for (int k = -Rr; k <= Rr; ++k) {
        const ptrdiff_t off = (ptrdiff_t)(o0 + k) * Wn;
        float4 v;
        v = ldh4(pc0 + off); ADD4(S0,v);
        v = ldh4(pc1 + off); ADD4(S1,v);
        v = ldh4(pc2 + off); ADD4(S2,v);
        v = ldh4(pc3 + off); ADD4(S3,v);
        v = ldh4(pc4 + off); ADD4(S4,v);
    }

    const float inv = 1.0f / 729.0f;
    float accf = 0.f;

    for (int o = o0; o < o0 + DCHUNK; ++o) {
        {
            const float mu1=S0.x*inv, mu2=S1.x*inv;
            const float v1=S2.x*inv-mu1*mu1, v2=S3.x*inv-mu2*mu2, cv=S4.x*inv-mu1*mu2;
            accf += __fdividef(cv*cv, v1*v2 + 1e-5f);
        }
        {
            const float mu1=S0.y*inv, mu2=S1.y*inv;
            const float v1=S2.y*inv-mu1*mu1, v2=S3.y*inv-mu2*mu2, cv=S4.y*inv-mu1*mu2;
            accf += __fdividef(cv*cv, v1*v2 + 1e-5f);
        }
        {
            const float mu1=S0.z*inv, mu2=S1.z*inv;
            const float v1=S2.z*inv-mu1*mu1, v2=S3.z*inv-mu2*mu2, cv=S4.z*inv-mu1*mu2;
            accf += __fdividef(cv*cv, v1*v2 + 1e-5f);
        }
        {
            const float mu1=S0.w*inv, mu2=S1.w*inv;
            const float v1=S2.w*inv-mu1*mu1, v2=S3.w*inv-mu2*mu2, cv=S4.w*inv-mu1*mu2;
            accf += __fdividef(cv*cv, v1*v2 + 1e-5f);
        }

        {
            const ptrdiff_t oa = (ptrdiff_t)(o + Rr + 1) * Wn;
            const ptrdiff_t os = (ptrdiff_t)(o - Rr) * Wn;
            float4 v;
            v = ldh4(pc0 + oa); ADD4(S0,v);
            v = ldh4(pc1 + oa); ADD4(S1,v);
            v = ldh4(pc2 + oa); ADD4(S2,v);
            v = ldh4(pc3 + oa); ADD4(S3,v);
            v = ldh4(pc4 + oa); ADD4(S4,v);
            v = ldh4(pc0 + os); SUB4(S0,v);
            v = ldh4(pc1 + os); SUB4(S1,v);
            v = ldh4(pc2 + os); SUB4(S2,v);
            v = ldh4(pc3 + os); SUB4(S3,v);
            v = ldh4(pc4 + os); SUB4(S4,v);
        }
    }

    // Deterministic block reduction (160 -> 1)
    __shared__ double red[160];
    const int w = tid;
    red[w] = (double)accf;
    __syncthreads();
    if (w < 32) red[w] += red[w + 128];
    __syncthreads();
#pragma unroll
    for (int s = 64; s > 0; s >>= 1) {
        if (w < s) red[w] += red[w + s];
        __syncthreads();
    }

    __shared__ int isLast;
    if (w == 0) {
        g_part[blk] = red[0];
        __threadfence();
        const unsigned v = atomicAdd(&g_done, 1u);
        isLast = (v == (unsigned)(gridDim.x - 1));
    }
    __syncthreads();

    if (isLast) {
        __threadfence();
        double a = 0.0;
        for (int i = w; i < NPART; i += 160) a += g_part[i];  // fixed order
        red[w] = a;
        __syncthreads();
        if (w < 32) red[w] += red[w + 128];
        __syncthreads();
#pragma unroll
        for (int s = 64; s > 0; s >>= 1) {
            if (w < s) red[w] += red[w + s];
            __syncthreads();
        }
        if (w == 0) {
            outscalar[0] = (float)(-red[0] / (double)NB);
            g_done = 0;   // reset for next graph replay
        }
    }
}

extern "C" void kernel_launch(void* const* d_in, const int* in_sizes, int n_in,
                              void* d_out, int out_size) {
    const float* I = (const float*)d_in[0];   // y_true
    const float* J = (const float*)d_in[1];   // y_pred
    float* out = (float*)d_out;

    void* bufraw;
    cudaGetSymbolAddress(&bufraw, g_buf);
    __half* buf = (__half*)bufraw;

    static int configured = 0;
    if (!configured) {
        cudaFuncSetAttribute(pass_wh,
                             cudaFuncAttributeMaxDynamicSharedMemorySize,
                             RING_BYTES);
        configured = 1;
    }

    pass_wh<<<Bn * Dn * HSPLIT, 160, RING_BYTES>>>(I, J, buf);
    pass_d_cc<<<Bn * (Hn/NROWS) * DSPLIT, 160>>>(buf, out);
}